// round 12
// baseline (speedup 1.0000x reference)
#include <cuda_runtime.h>
#include <cuda_bf16.h>

// Register-resident 512-pt FFT (radix 8x8x8): 64 threads/FFT, 8 complex/thread.
// Packed f32x2 butterflies, compile-time twiddle tables (smem-resident),
// per-group named barriers. [R10: R8 structure + forced 6 blocks/SM]

typedef unsigned long long ull;

// ---------- compile-time twiddle tables ----------
struct TwTab { float2 w[520]; };   // [0,448): Wr[(r-1)*64+t] = e^{-i2pi r t/512}
                                   // [448,520): T2[b*9+r]    = e^{-i2pi b r/64}
constexpr double TPI_D = 6.283185307179586476925286766559;
constexpr double tsin(double x) {
    double x2 = x * x, t = x, s = x;
    for (int k = 1; k <= 13; k++) { t = -t * x2 / ((2.0 * k) * (2.0 * k + 1.0)); s += t; }
    return s;
}
constexpr double tcos(double x) {
    double x2 = x * x, t = 1.0, s = 1.0;
    for (int k = 1; k <= 13; k++) { t = -t * x2 / ((2.0 * k - 1.0) * (2.0 * k)); s += t; }
    return s;
}
constexpr TwTab make_tab() {
    TwTab T{};
    for (int r = 1; r < 8; r++)
        for (int t = 0; t < 64; t++) {
            int m = (r * t) & 511; int mm = (m > 256) ? m - 512 : m;
            double a = -TPI_D * (double)mm / 512.0;
            T.w[(r - 1) * 64 + t].x = (float)tcos(a);
            T.w[(r - 1) * 64 + t].y = (float)tsin(a);
        }
    for (int b = 0; b < 8; b++)
        for (int r = 0; r < 9; r++) {
            int m = (b * (r & 7)) & 63; int mm = (m > 32) ? m - 64 : m;
            double a = -TPI_D * (double)mm / 64.0;
            T.w[448 + b * 9 + r].x = (float)tcos(a);
            T.w[448 + b * 9 + r].y = (float)tsin(a);
        }
    return T;
}
__device__ constexpr TwTab d_tw = make_tab();

// ---------- packed f32x2 helpers ----------
__device__ __forceinline__ ull PK2(float x, float y) {
    ull r; asm("mov.b64 %0, {%1, %2};" : "=l"(r) : "f"(x), "f"(y)); return r;
}
__device__ __forceinline__ void UPK(ull v, float& x, float& y) {
    asm("mov.b64 {%0, %1}, %2;" : "=f"(x), "=f"(y) : "l"(v));
}
__device__ __forceinline__ ull SWP(ull v) { float x, y; UPK(v, x, y); return PK2(y, x); }
__device__ __forceinline__ ull padd(ull a, ull b) {
    ull r; asm("add.rn.f32x2 %0, %1, %2;" : "=l"(r) : "l"(a), "l"(b)); return r;
}
__device__ __forceinline__ ull pmul(ull a, ull b) {
    ull r; asm("mul.rn.f32x2 %0, %1, %2;" : "=l"(r) : "l"(a), "l"(b)); return r;
}
__device__ __forceinline__ ull pfma(ull a, ull b, ull c) {
    ull r; asm("fma.rn.f32x2 %0, %1, %2, %3;" : "=l"(r) : "l"(a), "l"(b), "l"(c)); return r;
}

// Named barrier over one 64-thread FFT group (warps 2g, 2g+1).
__device__ __forceinline__ void gbar(int g) {
    asm volatile("bar.sync %0, 64;" :: "r"(g + 1) : "memory");
}

// ---------- packed radix-8 butterfly (verified lane-by-lane, both signs) ----------
template<int SGN>   // -1 = forward (e^{-i}), +1 = inverse (e^{+i})
__device__ __forceinline__ void radix8p(ull x[8]) {
    const ull NEG1 = PK2(-1.0f, -1.0f);
    const ull PM   = PK2( 1.0f, -1.0f);
    const ull MP   = PK2(-1.0f,  1.0f);
    const float Cq = 0.70710678118654752440f;
    const ull CC   = PK2(Cq, Cq);
    ull t0 = padd(x[0], x[4]), t4 = pfma(x[4], NEG1, x[0]);
    ull t1 = padd(x[1], x[5]), t5 = pfma(x[5], NEG1, x[1]);
    ull t2 = padd(x[2], x[6]), t6 = pfma(x[6], NEG1, x[2]);
    ull t3 = padd(x[3], x[7]), t7 = pfma(x[7], NEG1, x[3]);
    ull s5 = SWP(t5), s6 = SWP(t6), s7 = SWP(t7);
    ull t5r, t7r;
    if (SGN < 0) {
        t5r = pmul(pfma(s5, PM, t5), CC);
        t7r = pmul(pfma(t7, NEG1, pmul(s7, PM)), CC);
    } else {
        t5r = pmul(pfma(s5, MP, t5), CC);
        t7r = pmul(pfma(t7, NEG1, pmul(s7, MP)), CC);
    }
    ull u0 = padd(t0, t2), u2 = pfma(t2, NEG1, t0);
    ull u1 = padd(t1, t3), u3 = pfma(t3, NEG1, t1);
    ull v0, v2;
    if (SGN < 0) { v0 = pfma(s6, PM, t4); v2 = pfma(s6, MP, t4); }
    else         { v0 = pfma(s6, MP, t4); v2 = pfma(s6, PM, t4); }
    ull v1 = padd(t5r, t7r), v3 = pfma(t7r, NEG1, t5r);
    x[0] = padd(u0, u1); x[4] = pfma(u1, NEG1, u0);
    x[1] = padd(v0, v1); x[5] = pfma(v1, NEG1, v0);
    ull su3 = SWP(u3), sv3 = SWP(v3);
    if (SGN < 0) {
        x[2] = pfma(su3, PM, u2); x[6] = pfma(su3, MP, u2);
        x[3] = pfma(sv3, PM, v2); x[7] = pfma(sv3, MP, v2);
    } else {
        x[2] = pfma(su3, MP, u2); x[6] = pfma(su3, PM, u2);
        x[3] = pfma(sv3, MP, v2); x[7] = pfma(sv3, PM, v2);
    }
}

// Complex twiddle on a packed value: a * w (SGN<0) or a * conj(w) (SGN>0).
template<int SGN>
__device__ __forceinline__ float2 twid(ull a, float2 w) {
    float ax, ay; UPK(a, ax, ay);
    float2 r;
    if (SGN < 0) { r.x = fmaf(ax, w.x, -ay * w.y); r.y = fmaf(ax, w.y,  ay * w.x); }
    else         { r.x = fmaf(ax, w.x,  ay * w.y); r.y = fmaf(ay, w.x, -ax * w.y); }
    return r;
}

// Bank-conflict-free swizzled transpose addressing (verified per half-warp).
__device__ __forceinline__ int phys1(int k1, int n2) {
    return (k1 << 6) | (n2 ^ ((k1 & 1) << 3));
}
__device__ __forceinline__ int phys2i(int k1, int k1p, int b) {
    return (k1 << 6) | ((k1p >> 1) << 4) | (((k1 ^ k1p) & 1) << 3) | ((b ^ k1p) & 7);
}
__device__ __forceinline__ int physF(int k) {
    return k ^ (((k >> 4) & 3) << 1);
}

// 512-pt complex FFT across 64 threads. Input: x[r] = data[64r + t] (packed).
// Output: x[r] = F[(r<<6) + ((t&7)<<3) + (t>>3)]. 2 internal group barriers.
template<int SGN>
__device__ __forceinline__ void fft512(ull x[8], int t, int g,
                                       float2* bufT1, float2* bufT2,
                                       const float2* __restrict__ Wr,
                                       const float2* __restrict__ T2) {
    radix8p<SGN>(x);
    ull* T1u = (ull*)bufT1;
    T1u[phys1(0, t)] = x[0];                       // twiddle = 1: raw store
#pragma unroll
    for (int r = 1; r < 8; r++) bufT1[phys1(r, t)] = twid<SGN>(x[r], Wr[((r - 1) << 6) | t]);
    gbar(g);
    const int k1 = t >> 3, b = t & 7;
#pragma unroll
    for (int a = 0; a < 8; a++) x[a] = T1u[phys1(k1, (a << 3) | b)];
    radix8p<SGN>(x);
    ull* T2u = (ull*)bufT2;
    T2u[phys2i(k1, 0, b)] = x[0];                  // twiddle = 1: raw store
#pragma unroll
    for (int r = 1; r < 8; r++) bufT2[phys2i(k1, r, b)] = twid<SGN>(x[r], T2[b * 9 + r]);
    gbar(g);
#pragma unroll
    for (int bb = 0; bb < 8; bb++) x[bb] = T2u[phys2i(k1, b, bb)];
    radix8p<SGN>(x);
}

__global__ void __launch_bounds__(256, 6)   // force 6 blocks/SM (<=42 regs)
acf_kernel(const float2* __restrict__ in, float* __restrict__ out) {
    __shared__ float2 SM[2][4 * 520];   // ping-pong transpose buffers (4 FFT groups)
    __shared__ float2 TAB[520];         // Wr (448) + T2 (72)

    const int tid   = threadIdx.x;
    const int g     = tid >> 6;        // FFT group 0..3
    const int t     = tid & 63;        // lane within FFT
    const int frame = blockIdx.x * 4 + g;
    const int bf    = blockIdx.y;

    for (int i = tid; i < 520; i += 256) TAB[i] = d_tw.w[i];
    __syncthreads();
    const float2* Wr = TAB;
    const float2* T2 = TAB + 448;

    float2* smA = &SM[0][g * 520];
    float2* smB = &SM[1][g * 520];

    // Frame start: exact int match of np.linspace(0,19488,300).astype(int64).
    const int start = (19488 * frame) / 299;
    const ull* src = (const ull*)(in + ((long)bf * 20000 + start));

    // Load + Hann window. cos(2pi(64r+t)/512) = ca_r*w1.x + sa_r*w1.y, w1 = Wr[t].
    ull x[8];
    {
        const float2 w1 = Wr[t];
        const float CQ = 0.70710678118654752440f;
        const float ca[8] = {1.0f,  CQ, 0.0f, -CQ, -1.0f, -CQ,  0.0f,  CQ};
        const float sa[8] = {0.0f,  CQ, 1.0f,  CQ,  0.0f, -CQ, -1.0f, -CQ};
#pragma unroll
        for (int r = 0; r < 8; r++) {
            const float cosn = ca[r] * w1.x + sa[r] * w1.y;
            const float w = 0.5f - 0.5f * cosn;
            x[r] = pmul(src[(r << 6) + t], PK2(w, w));
        }
    }

    // Forward FFT. Output: x[r] = F[k], k = 64r + 8*(t&7) + (t>>3).
    fft512<-1>(x, t, g, smA, smB, Wr, T2);

    // Store F at natural k (swizzled).
    const int klo = ((t & 7) << 3) | (t >> 3);
    ull* smAu = (ull*)smA;
#pragma unroll
    for (int r = 0; r < 8; r++) smAu[physF((r << 6) + klo)] = x[r];
    gbar(g);

    // Hermitian split + power spectra (packed): S=Fk+Fm, D=Fk-Fm,
    // (p0,p1) = 0.25*(S*S + swap(D*D)).  x[r] = Q[64r + t] (inverse input layout).
    {
        const ull NEG1 = PK2(-1.0f, -1.0f);
        const ull QQ   = PK2(0.25f, 0.25f);
#pragma unroll
        for (int r = 0; r < 8; r++) {
            const int k  = (r << 6) + t;
            const int kk = (512 - k) & 511;
            const ull Fk = smAu[physF(k)];
            const ull Fm = smAu[physF(kk)];
            const ull S = padd(Fk, Fm);
            const ull D = pfma(Fm, NEG1, Fk);
            x[r] = pmul(padd(pmul(S, S), SWP(pmul(D, D))), QQ);
        }
    }

    // Inverse FFT. Output: x[c] = 512*(acf0 + i*acf1)[n], n = 64c + klo.
    fft512<+1>(x, t, g, smB, smA, Wr, T2);

    // Broadcast acf[0] (held by t==0, reg 0).
    if (t == 0) *(ull*)&smB[512] = x[0];
    gbar(g);

    const float inv = 1.0f / 512.0f;
    const float2 q0 = smB[512];
    const float n0 = fmaxf(q0.x * inv, 0.0f);
    const float n1 = fmaxf(q0.y * inv, 0.0f);
    const float s0 = (n0 == 0.0f) ? 1.0f : rsqrtf(n0);
    const float s1 = (n1 == 0.0f) ? 1.0f : rsqrtf(n1);

    float* op = out + ((long)bf * 300 + frame) * 256;
#pragma unroll
    for (int c = 0; c < 4; c++) {            // lags 0..255 <=> c < 4
        float qx, qy; UPK(x[c], qx, qy);
        const float a0 = fmaxf(qx * inv, 0.0f) * s0;
        const float a1 = fmaxf(qy * inv, 0.0f) * s1;
        op[(c << 6) + klo] = 0.5f * (a0 + a1);
    }
}

extern "C" void kernel_launch(void* const* d_in, const int* in_sizes, int n_in,
                              void* d_out, int out_size) {
    const float2* in = (const float2*)d_in[0];  // (4,50,20000,2) fp32 as float2
    float* out = (float*)d_out;                 // (4,50,300,256) fp32
    dim3 grid(75, 200, 1);                      // 75*4 frames, 200 (b,f) pairs
    acf_kernel<<<grid, 256>>>(in, out);
}

// round 15
// speedup vs baseline: 1.0992x; 1.0992x over previous
#include <cuda_runtime.h>
#include <cuda_bf16.h>

// Register-resident 512-pt FFT (radix 8x8x8): 64 threads/FFT, 8 complex/thread.
// Packed f32x2 butterflies, compile-time twiddle tables (smem-resident),
// per-group named barriers.
// [R13: 192-thread blocks (3 FFT groups) -> 7 blocks/SM, 42 resident warps]

typedef unsigned long long ull;

#define NGROUP 3
#define NTHREADS (NGROUP * 64)

// ---------- compile-time twiddle tables ----------
struct TwTab { float2 w[520]; };   // [0,448): Wr[(r-1)*64+t] = e^{-i2pi r t/512}
                                   // [448,520): T2[b*9+r]    = e^{-i2pi b r/64}
constexpr double TPI_D = 6.283185307179586476925286766559;
constexpr double tsin(double x) {
    double x2 = x * x, t = x, s = x;
    for (int k = 1; k <= 13; k++) { t = -t * x2 / ((2.0 * k) * (2.0 * k + 1.0)); s += t; }
    return s;
}
constexpr double tcos(double x) {
    double x2 = x * x, t = 1.0, s = 1.0;
    for (int k = 1; k <= 13; k++) { t = -t * x2 / ((2.0 * k - 1.0) * (2.0 * k)); s += t; }
    return s;
}
constexpr TwTab make_tab() {
    TwTab T{};
    for (int r = 1; r < 8; r++)
        for (int t = 0; t < 64; t++) {
            int m = (r * t) & 511; int mm = (m > 256) ? m - 512 : m;
            double a = -TPI_D * (double)mm / 512.0;
            T.w[(r - 1) * 64 + t].x = (float)tcos(a);
            T.w[(r - 1) * 64 + t].y = (float)tsin(a);
        }
    for (int b = 0; b < 8; b++)
        for (int r = 0; r < 9; r++) {
            int m = (b * (r & 7)) & 63; int mm = (m > 32) ? m - 64 : m;
            double a = -TPI_D * (double)mm / 64.0;
            T.w[448 + b * 9 + r].x = (float)tcos(a);
            T.w[448 + b * 9 + r].y = (float)tsin(a);
        }
    return T;
}
__device__ constexpr TwTab d_tw = make_tab();

// ---------- packed f32x2 helpers ----------
__device__ __forceinline__ ull PK2(float x, float y) {
    ull r; asm("mov.b64 %0, {%1, %2};" : "=l"(r) : "f"(x), "f"(y)); return r;
}
__device__ __forceinline__ void UPK(ull v, float& x, float& y) {
    asm("mov.b64 {%0, %1}, %2;" : "=f"(x), "=f"(y) : "l"(v));
}
__device__ __forceinline__ ull SWP(ull v) { float x, y; UPK(v, x, y); return PK2(y, x); }
__device__ __forceinline__ ull padd(ull a, ull b) {
    ull r; asm("add.rn.f32x2 %0, %1, %2;" : "=l"(r) : "l"(a), "l"(b)); return r;
}
__device__ __forceinline__ ull pmul(ull a, ull b) {
    ull r; asm("mul.rn.f32x2 %0, %1, %2;" : "=l"(r) : "l"(a), "l"(b)); return r;
}
__device__ __forceinline__ ull pfma(ull a, ull b, ull c) {
    ull r; asm("fma.rn.f32x2 %0, %1, %2, %3;" : "=l"(r) : "l"(a), "l"(b), "l"(c)); return r;
}

// Named barrier over one 64-thread FFT group (warps 2g, 2g+1).
__device__ __forceinline__ void gbar(int g) {
    asm volatile("bar.sync %0, 64;" :: "r"(g + 1) : "memory");
}

// ---------- packed radix-8 butterfly (verified lane-by-lane, both signs) ----------
template<int SGN>   // -1 = forward (e^{-i}), +1 = inverse (e^{+i})
__device__ __forceinline__ void radix8p(ull x[8]) {
    const ull NEG1 = PK2(-1.0f, -1.0f);
    const ull PM   = PK2( 1.0f, -1.0f);
    const ull MP   = PK2(-1.0f,  1.0f);
    const float Cq = 0.70710678118654752440f;
    const ull CC   = PK2(Cq, Cq);
    ull t0 = padd(x[0], x[4]), t4 = pfma(x[4], NEG1, x[0]);
    ull t1 = padd(x[1], x[5]), t5 = pfma(x[5], NEG1, x[1]);
    ull t2 = padd(x[2], x[6]), t6 = pfma(x[6], NEG1, x[2]);
    ull t3 = padd(x[3], x[7]), t7 = pfma(x[7], NEG1, x[3]);
    ull s5 = SWP(t5), s6 = SWP(t6), s7 = SWP(t7);
    ull t5r, t7r;
    if (SGN < 0) {
        t5r = pmul(pfma(s5, PM, t5), CC);
        t7r = pmul(pfma(t7, NEG1, pmul(s7, PM)), CC);
    } else {
        t5r = pmul(pfma(s5, MP, t5), CC);
        t7r = pmul(pfma(t7, NEG1, pmul(s7, MP)), CC);
    }
    ull u0 = padd(t0, t2), u2 = pfma(t2, NEG1, t0);
    ull u1 = padd(t1, t3), u3 = pfma(t3, NEG1, t1);
    ull v0, v2;
    if (SGN < 0) { v0 = pfma(s6, PM, t4); v2 = pfma(s6, MP, t4); }
    else         { v0 = pfma(s6, MP, t4); v2 = pfma(s6, PM, t4); }
    ull v1 = padd(t5r, t7r), v3 = pfma(t7r, NEG1, t5r);
    x[0] = padd(u0, u1); x[4] = pfma(u1, NEG1, u0);
    x[1] = padd(v0, v1); x[5] = pfma(v1, NEG1, v0);
    ull su3 = SWP(u3), sv3 = SWP(v3);
    if (SGN < 0) {
        x[2] = pfma(su3, PM, u2); x[6] = pfma(su3, MP, u2);
        x[3] = pfma(sv3, PM, v2); x[7] = pfma(sv3, MP, v2);
    } else {
        x[2] = pfma(su3, MP, u2); x[6] = pfma(su3, PM, u2);
        x[3] = pfma(sv3, MP, v2); x[7] = pfma(sv3, PM, v2);
    }
}

// Complex twiddle on a packed value: a * w (SGN<0) or a * conj(w) (SGN>0).
template<int SGN>
__device__ __forceinline__ float2 twid(ull a, float2 w) {
    float ax, ay; UPK(a, ax, ay);
    float2 r;
    if (SGN < 0) { r.x = fmaf(ax, w.x, -ay * w.y); r.y = fmaf(ax, w.y,  ay * w.x); }
    else         { r.x = fmaf(ax, w.x,  ay * w.y); r.y = fmaf(ay, w.x, -ax * w.y); }
    return r;
}

// Bank-conflict-free swizzled transpose addressing (verified per half-warp).
__device__ __forceinline__ int phys1(int k1, int n2) {
    return (k1 << 6) | (n2 ^ ((k1 & 1) << 3));
}
__device__ __forceinline__ int phys2i(int k1, int k1p, int b) {
    return (k1 << 6) | ((k1p >> 1) << 4) | (((k1 ^ k1p) & 1) << 3) | ((b ^ k1p) & 7);
}
__device__ __forceinline__ int physF(int k) {
    return k ^ (((k >> 4) & 3) << 1);
}

// 512-pt complex FFT across 64 threads. Input: x[r] = data[64r + t] (packed).
// Output: x[r] = F[(r<<6) + ((t&7)<<3) + (t>>3)]. 2 internal group barriers.
template<int SGN>
__device__ __forceinline__ void fft512(ull x[8], int t, int g,
                                       float2* bufT1, float2* bufT2,
                                       const float2* __restrict__ Wr,
                                       const float2* __restrict__ T2) {
    radix8p<SGN>(x);
    ull* T1u = (ull*)bufT1;
    T1u[phys1(0, t)] = x[0];                       // twiddle = 1: raw store
#pragma unroll
    for (int r = 1; r < 8; r++) bufT1[phys1(r, t)] = twid<SGN>(x[r], Wr[((r - 1) << 6) | t]);
    gbar(g);
    const int k1 = t >> 3, b = t & 7;
#pragma unroll
    for (int a = 0; a < 8; a++) x[a] = T1u[phys1(k1, (a << 3) | b)];
    radix8p<SGN>(x);
    ull* T2u = (ull*)bufT2;
    T2u[phys2i(k1, 0, b)] = x[0];                  // twiddle = 1: raw store
#pragma unroll
    for (int r = 1; r < 8; r++) bufT2[phys2i(k1, r, b)] = twid<SGN>(x[r], T2[b * 9 + r]);
    gbar(g);
#pragma unroll
    for (int bb = 0; bb < 8; bb++) x[bb] = T2u[phys2i(k1, b, bb)];
    radix8p<SGN>(x);
}

__global__ void __launch_bounds__(NTHREADS)
acf_kernel(const float2* __restrict__ in, float* __restrict__ out) {
    __shared__ float2 SM[2][NGROUP * 520];  // ping-pong transpose buffers
    __shared__ float2 TAB[520];             // Wr (448) + T2 (72)

    const int tid   = threadIdx.x;
    const int g     = tid >> 6;        // FFT group 0..NGROUP-1
    const int t     = tid & 63;        // lane within FFT
    const int frame = blockIdx.x * NGROUP + g;
    const int bf    = blockIdx.y;

    for (int i = tid; i < 520; i += NTHREADS) TAB[i] = d_tw.w[i];
    __syncthreads();
    const float2* Wr = TAB;
    const float2* T2 = TAB + 448;

    float2* smA = &SM[0][g * 520];
    float2* smB = &SM[1][g * 520];

    // Frame start: exact int match of np.linspace(0,19488,300).astype(int64).
    const int start = (19488 * frame) / 299;
    const ull* src = (const ull*)(in + ((long)bf * 20000 + start));

    // Load + Hann window. cos(2pi(64r+t)/512) = ca_r*w1.x + sa_r*w1.y, w1 = Wr[t].
    ull x[8];
    {
        const float2 w1 = Wr[t];
        const float CQ = 0.70710678118654752440f;
        const float ca[8] = {1.0f,  CQ, 0.0f, -CQ, -1.0f, -CQ,  0.0f,  CQ};
        const float sa[8] = {0.0f,  CQ, 1.0f,  CQ,  0.0f, -CQ, -1.0f, -CQ};
#pragma unroll
        for (int r = 0; r < 8; r++) {
            const float cosn = ca[r] * w1.x + sa[r] * w1.y;
            const float w = 0.5f - 0.5f * cosn;
            x[r] = pmul(src[(r << 6) + t], PK2(w, w));
        }
    }

    // Forward FFT. Output: x[r] = F[k], k = 64r + 8*(t&7) + (t>>3).
    fft512<-1>(x, t, g, smA, smB, Wr, T2);

    // Store F at natural k (swizzled).
    const int klo = ((t & 7) << 3) | (t >> 3);
    ull* smAu = (ull*)smA;
#pragma unroll
    for (int r = 0; r < 8; r++) smAu[physF((r << 6) + klo)] = x[r];
    gbar(g);

    // Hermitian split + power spectra (packed): S=Fk+Fm, D=Fk-Fm,
    // (p0,p1) = 0.25*(S*S + swap(D*D)).  x[r] = Q[64r + t] (inverse input layout).
    {
        const ull NEG1 = PK2(-1.0f, -1.0f);
        const ull QQ   = PK2(0.25f, 0.25f);
#pragma unroll
        for (int r = 0; r < 8; r++) {
            const int k  = (r << 6) + t;
            const int kk = (512 - k) & 511;
            const ull Fk = smAu[physF(k)];
            const ull Fm = smAu[physF(kk)];
            const ull S = padd(Fk, Fm);
            const ull D = pfma(Fm, NEG1, Fk);
            x[r] = pmul(padd(pmul(S, S), SWP(pmul(D, D))), QQ);
        }
    }

    // Inverse FFT. Output: x[c] = 512*(acf0 + i*acf1)[n], n = 64c + klo.
    fft512<+1>(x, t, g, smB, smA, Wr, T2);

    // Broadcast acf[0] (held by t==0, reg 0).
    if (t == 0) *(ull*)&smB[512] = x[0];
    gbar(g);

    const float inv = 1.0f / 512.0f;
    const float2 q0 = smB[512];
    const float n0 = fmaxf(q0.x * inv, 0.0f);
    const float n1 = fmaxf(q0.y * inv, 0.0f);
    const float s0 = (n0 == 0.0f) ? 1.0f : rsqrtf(n0);
    const float s1 = (n1 == 0.0f) ? 1.0f : rsqrtf(n1);

    float* op = out + ((long)bf * 300 + frame) * 256;
#pragma unroll
    for (int c = 0; c < 4; c++) {            // lags 0..255 <=> c < 4
        float qx, qy; UPK(x[c], qx, qy);
        const float a0 = fmaxf(qx * inv, 0.0f) * s0;
        const float a1 = fmaxf(qy * inv, 0.0f) * s1;
        op[(c << 6) + klo] = 0.5f * (a0 + a1);
    }
}

extern "C" void kernel_launch(void* const* d_in, const int* in_sizes, int n_in,
                              void* d_out, int out_size) {
    const float2* in = (const float2*)d_in[0];  // (4,50,20000,2) fp32 as float2
    float* out = (float*)d_out;                 // (4,50,300,256) fp32
    dim3 grid(100, 200, 1);                     // 100*3 frames, 200 (b,f) pairs
    acf_kernel<<<grid, NTHREADS>>>(in, out);
}

// round 17
// speedup vs baseline: 1.2124x; 1.1030x over previous
#include <cuda_runtime.h>
#include <cuda_bf16.h>

// Register-resident 512-pt FFT (radix 8x8x8): 64 threads/FFT, 8 complex/thread.
// Packed f32x2 butterflies, compile-time twiddle tables, per-group named barriers.
// [R16] Transpose stages stored as packed fp16 (complex -> one 32-bit word):
// halves transpose smem traffic. All arithmetic, twiddles, and the Hermitian
// power-spectrum exchange remain fp32. New 4B-element bank-conflict-free maps.

typedef unsigned long long ull;

// ---------- compile-time twiddle tables ----------
struct TwTab { float2 w[520]; };   // [0,448): Wr[(r-1)*64+t] = e^{-i2pi r t/512}
                                   // [448,520): T2[b*9+r]    = e^{-i2pi b r/64}
constexpr double TPI_D = 6.283185307179586476925286766559;
constexpr double tsin(double x) {
    double x2 = x * x, t = x, s = x;
    for (int k = 1; k <= 13; k++) { t = -t * x2 / ((2.0 * k) * (2.0 * k + 1.0)); s += t; }
    return s;
}
constexpr double tcos(double x) {
    double x2 = x * x, t = 1.0, s = 1.0;
    for (int k = 1; k <= 13; k++) { t = -t * x2 / ((2.0 * k - 1.0) * (2.0 * k)); s += t; }
    return s;
}
constexpr TwTab make_tab() {
    TwTab T{};
    for (int r = 1; r < 8; r++)
        for (int t = 0; t < 64; t++) {
            int m = (r * t) & 511; int mm = (m > 256) ? m - 512 : m;
            double a = -TPI_D * (double)mm / 512.0;
            T.w[(r - 1) * 64 + t].x = (float)tcos(a);
            T.w[(r - 1) * 64 + t].y = (float)tsin(a);
        }
    for (int b = 0; b < 8; b++)
        for (int r = 0; r < 9; r++) {
            int m = (b * (r & 7)) & 63; int mm = (m > 32) ? m - 64 : m;
            double a = -TPI_D * (double)mm / 64.0;
            T.w[448 + b * 9 + r].x = (float)tcos(a);
            T.w[448 + b * 9 + r].y = (float)tsin(a);
        }
    return T;
}
__device__ constexpr TwTab d_tw = make_tab();

// ---------- packed f32x2 helpers ----------
__device__ __forceinline__ ull PK2(float x, float y) {
    ull r; asm("mov.b64 %0, {%1, %2};" : "=l"(r) : "f"(x), "f"(y)); return r;
}
__device__ __forceinline__ void UPK(ull v, float& x, float& y) {
    asm("mov.b64 {%0, %1}, %2;" : "=f"(x), "=f"(y) : "l"(v));
}
__device__ __forceinline__ ull SWP(ull v) { float x, y; UPK(v, x, y); return PK2(y, x); }
__device__ __forceinline__ ull padd(ull a, ull b) {
    ull r; asm("add.rn.f32x2 %0, %1, %2;" : "=l"(r) : "l"(a), "l"(b)); return r;
}
__device__ __forceinline__ ull pmul(ull a, ull b) {
    ull r; asm("mul.rn.f32x2 %0, %1, %2;" : "=l"(r) : "l"(a), "l"(b)); return r;
}
__device__ __forceinline__ ull pfma(ull a, ull b, ull c) {
    ull r; asm("fma.rn.f32x2 %0, %1, %2, %3;" : "=l"(r) : "l"(a), "l"(b), "l"(c)); return r;
}

// ---------- fp16 pack/unpack (complex <-> one 32-bit word) ----------
__device__ __forceinline__ unsigned pack16(float2 v) {
    unsigned r;
    asm("cvt.rn.f16x2.f32 %0, %1, %2;" : "=r"(r) : "f"(v.y), "f"(v.x));  // hi=y, lo=x
    return r;
}
__device__ __forceinline__ unsigned pack16u(ull v) {
    float x, y; UPK(v, x, y);
    return pack16(make_float2(x, y));
}
__device__ __forceinline__ ull unpack16(unsigned p) {
    float x, y;
    asm("{\n\t.reg .b16 lo, hi;\n\tmov.b32 {lo, hi}, %2;\n\t"
        "cvt.f32.f16 %0, lo;\n\tcvt.f32.f16 %1, hi;\n\t}"
        : "=f"(x), "=f"(y) : "r"(p));
    return PK2(x, y);
}

// Named barrier over one 64-thread FFT group (warps 2g, 2g+1).
__device__ __forceinline__ void gbar(int g) {
    asm volatile("bar.sync %0, 64;" :: "r"(g + 1) : "memory");
}

// ---------- packed radix-8 butterfly (verified lane-by-lane, both signs) ----------
template<int SGN>   // -1 = forward (e^{-i}), +1 = inverse (e^{+i})
__device__ __forceinline__ void radix8p(ull x[8]) {
    const ull NEG1 = PK2(-1.0f, -1.0f);
    const ull PM   = PK2( 1.0f, -1.0f);
    const ull MP   = PK2(-1.0f,  1.0f);
    const float Cq = 0.70710678118654752440f;
    const ull CC   = PK2(Cq, Cq);
    ull t0 = padd(x[0], x[4]), t4 = pfma(x[4], NEG1, x[0]);
    ull t1 = padd(x[1], x[5]), t5 = pfma(x[5], NEG1, x[1]);
    ull t2 = padd(x[2], x[6]), t6 = pfma(x[6], NEG1, x[2]);
    ull t3 = padd(x[3], x[7]), t7 = pfma(x[7], NEG1, x[3]);
    ull s5 = SWP(t5), s6 = SWP(t6), s7 = SWP(t7);
    ull t5r, t7r;
    if (SGN < 0) {
        t5r = pmul(pfma(s5, PM, t5), CC);
        t7r = pmul(pfma(t7, NEG1, pmul(s7, PM)), CC);
    } else {
        t5r = pmul(pfma(s5, MP, t5), CC);
        t7r = pmul(pfma(t7, NEG1, pmul(s7, MP)), CC);
    }
    ull u0 = padd(t0, t2), u2 = pfma(t2, NEG1, t0);
    ull u1 = padd(t1, t3), u3 = pfma(t3, NEG1, t1);
    ull v0, v2;
    if (SGN < 0) { v0 = pfma(s6, PM, t4); v2 = pfma(s6, MP, t4); }
    else         { v0 = pfma(s6, MP, t4); v2 = pfma(s6, PM, t4); }
    ull v1 = padd(t5r, t7r), v3 = pfma(t7r, NEG1, t5r);
    x[0] = padd(u0, u1); x[4] = pfma(u1, NEG1, u0);
    x[1] = padd(v0, v1); x[5] = pfma(v1, NEG1, v0);
    ull su3 = SWP(u3), sv3 = SWP(v3);
    if (SGN < 0) {
        x[2] = pfma(su3, PM, u2); x[6] = pfma(su3, MP, u2);
        x[3] = pfma(sv3, PM, v2); x[7] = pfma(sv3, MP, v2);
    } else {
        x[2] = pfma(su3, MP, u2); x[6] = pfma(su3, PM, u2);
        x[3] = pfma(sv3, MP, v2); x[7] = pfma(sv3, PM, v2);
    }
}

// Complex twiddle on a packed value: a * w (SGN<0) or a * conj(w) (SGN>0).
template<int SGN>
__device__ __forceinline__ float2 twid(ull a, float2 w) {
    float ax, ay; UPK(a, ax, ay);
    float2 r;
    if (SGN < 0) { r.x = fmaf(ax, w.x, -ay * w.y); r.y = fmaf(ax, w.y,  ay * w.x); }
    else         { r.x = fmaf(ax, w.x,  ay * w.y); r.y = fmaf(ay, w.x, -ax * w.y); }
    return r;
}

// ---- 4B-element bank-conflict-free maps (verified: all 32 banks distinct
//      for every read and write pattern; bijective on [0,512)) ----
__device__ __forceinline__ int aT1(int r, int c) {           // row 0..7, col 0..63
    return (r << 6) | (c ^ ((r & 3) << 3));
}
__device__ __forceinline__ int aT2(int k1, int k1p, int b) { // each 0..7
    return ((k1 >> 2) << 8) | (k1p << 5) | ((k1 & 3) << 3) | ((k1p ^ b) & 7);
}
// Hermitian exchange buffer stays fp32 (8B): champion's verified map.
__device__ __forceinline__ int physF(int k) {
    return k ^ (((k >> 4) & 3) << 1);
}

// 512-pt complex FFT across 64 threads, fp16 transpose storage.
// Input: x[r] = data[64r + t] (packed f32x2). Output: x[r] = F[64r + klo(t)].
template<int SGN>
__device__ __forceinline__ void fft512h(ull x[8], int t, int g,
                                        unsigned* bufT1, unsigned* bufT2,
                                        const float2* __restrict__ Wr,
                                        const float2* __restrict__ T2tab) {
    radix8p<SGN>(x);
    bufT1[aT1(0, t)] = pack16u(x[0]);
#pragma unroll
    for (int r = 1; r < 8; r++)
        bufT1[aT1(r, t)] = pack16(twid<SGN>(x[r], Wr[((r - 1) << 6) | t]));
    gbar(g);
    const int k1 = t >> 3, b = t & 7;
#pragma unroll
    for (int a = 0; a < 8; a++) x[a] = unpack16(bufT1[aT1(k1, (a << 3) | b)]);
    radix8p<SGN>(x);
    bufT2[aT2(k1, 0, b)] = pack16u(x[0]);
#pragma unroll
    for (int r = 1; r < 8; r++)
        bufT2[aT2(k1, r, b)] = pack16(twid<SGN>(x[r], T2tab[b * 9 + r]));
    gbar(g);
#pragma unroll
    for (int bb = 0; bb < 8; bb++) x[bb] = unpack16(bufT2[aT2(k1, b, bb)]);
    radix8p<SGN>(x);
}

__global__ void __launch_bounds__(256)
acf_kernel(const float2* __restrict__ in, float* __restrict__ out) {
    __shared__ unsigned HB[2][4 * 520];   // fp16 ping-pong transpose buffers
    __shared__ float2 FB[4 * 520];        // fp32 Hermitian exchange (+bcast slot)
    __shared__ float2 TAB[520];           // Wr (448) + T2 (72), fp32

    const int tid   = threadIdx.x;
    const int g     = tid >> 6;        // FFT group 0..3
    const int t     = tid & 63;        // lane within FFT
    const int frame = blockIdx.x * 4 + g;
    const int bf    = blockIdx.y;

    for (int i = tid; i < 520; i += 256) TAB[i] = d_tw.w[i];
    __syncthreads();
    const float2* Wr = TAB;
    const float2* T2 = TAB + 448;

    unsigned* h1 = &HB[0][g * 520];
    unsigned* h2 = &HB[1][g * 520];
    float2*   fb = &FB[g * 520];

    // Frame start: exact int match of np.linspace(0,19488,300).astype(int64).
    const int start = (19488 * frame) / 299;
    const ull* src = (const ull*)(in + ((long)bf * 20000 + start));

    // Load + Hann window. cos(2pi(64r+t)/512) = ca_r*w1.x + sa_r*w1.y, w1 = Wr[t].
    ull x[8];
    {
        const float2 w1 = Wr[t];
        const float CQ = 0.70710678118654752440f;
        const float ca[8] = {1.0f,  CQ, 0.0f, -CQ, -1.0f, -CQ,  0.0f,  CQ};
        const float sa[8] = {0.0f,  CQ, 1.0f,  CQ,  0.0f, -CQ, -1.0f, -CQ};
#pragma unroll
        for (int r = 0; r < 8; r++) {
            const float cosn = ca[r] * w1.x + sa[r] * w1.y;
            const float w = 0.5f - 0.5f * cosn;
            x[r] = pmul(src[(r << 6) + t], PK2(w, w));
        }
    }

    // Forward FFT. Output: x[r] = F[k], k = 64r + 8*(t&7) + (t>>3).
    fft512h<-1>(x, t, g, h1, h2, Wr, T2);

    // Store F at natural k (fp32, swizzled) for the Hermitian exchange.
    const int klo = ((t & 7) << 3) | (t >> 3);
    ull* fbu = (ull*)fb;
#pragma unroll
    for (int r = 0; r < 8; r++) fbu[physF((r << 6) + klo)] = x[r];
    gbar(g);

    // Hermitian split + power spectra (fp32): S=Fk+Fm, D=Fk-Fm,
    // (p0,p1) = 0.25*(S*S + swap(D*D)).  x[r] = Q[64r + t] (inverse input layout).
    {
        const ull NEG1 = PK2(-1.0f, -1.0f);
        const ull QQ   = PK2(0.25f, 0.25f);
#pragma unroll
        for (int r = 0; r < 8; r++) {
            const int k  = (r << 6) + t;
            const int kk = (512 - k) & 511;
            const ull Fk = fbu[physF(k)];
            const ull Fm = fbu[physF(kk)];
            const ull S = padd(Fk, Fm);
            const ull D = pfma(Fm, NEG1, Fk);
            x[r] = pmul(padd(pmul(S, S), SWP(pmul(D, D))), QQ);
        }
    }
    gbar(g);   // fb reads done before inverse reuses nothing; keeps h-buffers free

    // Inverse FFT. Output: x[c] = 512*(acf0 + i*acf1)[n], n = 64c + klo.
    fft512h<+1>(x, t, g, h1, h2, Wr, T2);

    // Broadcast acf[0] (held by t==0, reg 0) via the fp32 buffer.
    if (t == 0) fbu[512] = x[0];
    gbar(g);

    const float inv = 1.0f / 512.0f;
    const float2 q0 = fb[512];
    const float n0 = fmaxf(q0.x * inv, 0.0f);
    const float n1 = fmaxf(q0.y * inv, 0.0f);
    const float s0 = (n0 == 0.0f) ? 1.0f : rsqrtf(n0);
    const float s1 = (n1 == 0.0f) ? 1.0f : rsqrtf(n1);

    float* op = out + ((long)bf * 300 + frame) * 256;
#pragma unroll
    for (int c = 0; c < 4; c++) {            // lags 0..255 <=> c < 4
        float qx, qy; UPK(x[c], qx, qy);
        const float a0 = fmaxf(qx * inv, 0.0f) * s0;
        const float a1 = fmaxf(qy * inv, 0.0f) * s1;
        op[(c << 6) + klo] = 0.5f * (a0 + a1);
    }
}

extern "C" void kernel_launch(void* const* d_in, const int* in_sizes, int n_in,
                              void* d_out, int out_size) {
    const float2* in = (const float2*)d_in[0];  // (4,50,20000,2) fp32 as float2
    float* out = (float*)d_out;                 // (4,50,300,256) fp32
    dim3 grid(75, 200, 1);                      // 75*4 frames, 200 (b,f) pairs
    acf_kernel<<<grid, 256>>>(in, out);
}